// round 14
// baseline (speedup 1.0000x reference)
#include <cuda_runtime.h>
#include <cstdint>

// out = X * W[idx][0] + Y * W[idx][1], idx = reward[b,s] in {0,1}
// X,Y: (4,4096,2048) fp32; reward: (4,4096,1) int32; W: (2,2) fp32.
//
// MLP=6 interpolation point (sweep so far: MLP2 74.7%, MLP4 85%, MLP8 79%).
// 256-thread block covers 1536 contiguous float4 = exactly 3 rows.
// 3 float4 X + 3 float4 Y front-batched per thread; all accesses fully
// coalesced 512B wavefronts. Tail block predicated (16384 % 3 != 0).

__global__ __launch_bounds__(256)
void blend_kernel_m6(const float4* __restrict__ X,
                     const float4* __restrict__ Y,
                     const int* __restrict__ reward,
                     const float* __restrict__ W,
                     float4* __restrict__ out,
                     int n4)
{
    int base = blockIdx.x * 1536 + threadIdx.x;

    int row0 = blockIdx.x * 3;
    int nrows = n4 >> 9;

    // Rows 0..2 of this block (guard the tail block).
    int idx0 = (reward[row0] != 0) ? 1 : 0;
    int idx1 = (row0 + 1 < nrows) ? ((reward[row0 + 1] != 0) ? 1 : 0) : 0;
    int idx2 = (row0 + 2 < nrows) ? ((reward[row0 + 2] != 0) ? 1 : 0) : 0;

    float a0 = W[2 * idx0], b0 = W[2 * idx0 + 1];
    float a1 = W[2 * idx1], b1 = W[2 * idx1 + 1];
    float a2 = W[2 * idx2], b2 = W[2 * idx2 + 1];

    bool p0 = (base          < n4);
    bool p1 = (base + 512    < n4);
    bool p2 = (base + 1024   < n4);

    // Front-batch up to 6 global loads (MLP=6).
    float4 x0, x1, x2, y0, y1, y2;
    if (p0) { x0 = X[base];        y0 = Y[base]; }
    if (p1) { x1 = X[base + 512];  y1 = Y[base + 512]; }
    if (p2) { x2 = X[base + 1024]; y2 = Y[base + 1024]; }

    // Per-offset row: offsets {0,256}->row0, {512,768}->row1, {1024,1280}->row2.
    // With tid<256, offset k*256 for k=0..5; but we use stride 512 pairs:
    // base+0 covers cols [0,256) of row0... actually offsets 0 and 256 both in
    // row0 requires 6 separate loads. Use 6 explicit offsets:
    // Simpler correct mapping below (k*256):
    (void)0;

    float4 o;
    if (p0) {
        o.x = fmaf(x0.x, a0, y0.x * b0);
        o.y = fmaf(x0.y, a0, y0.y * b0);
        o.z = fmaf(x0.z, a0, y0.z * b0);
        o.w = fmaf(x0.w, a0, y0.w * b0);
        out[base] = o;
    }
    if (p1) {
        o.x = fmaf(x1.x, a1, y1.x * b1);
        o.y = fmaf(x1.y, a1, y1.y * b1);
        o.z = fmaf(x1.z, a1, y1.z * b1);
        o.w = fmaf(x1.w, a1, y1.w * b1);
        out[base + 512] = o;
    }
    if (p2) {
        o.x = fmaf(x2.x, a2, y2.x * b2);
        o.y = fmaf(x2.y, a2, y2.y * b2);
        o.z = fmaf(x2.z, a2, y2.z * b2);
        o.w = fmaf(x2.w, a2, y2.w * b2);
        out[base + 1024] = o;
    }
}

// NOTE on mapping: with 256 threads and stride-512 offsets, thread tid covers
// float4 indices base, base+512, base+1024 — i.e. cols [tid] of rows
// row0,row0+1,row0+2 ... but a row is 512 float4 wide, so offset 0 covers only
// cols [0,256) of row0 and offset 512 covers cols [0,256) of row1? No:
// base = bid*1536 + tid with tid in [0,256) covers [bid*1536, bid*1536+256)
// = first half of row 3*bid. base+512 covers [.. +512, ..+768) = second half
// of row 3*bid ... This is wrong for the row->coefficient mapping above.
// CORRECTED mapping is implemented in blend_kernel_m6b below, which is the
// kernel actually launched.

__global__ __launch_bounds__(256)
void blend_kernel_m6b(const float4* __restrict__ X,
                      const float4* __restrict__ Y,
                      const int* __restrict__ reward,
                      const float* __restrict__ W,
                      float4* __restrict__ out,
                      int n4)
{
    int blk = blockIdx.x * 1536;
    int tid = threadIdx.x;
    int row0 = blockIdx.x * 3;
    int nrows = n4 >> 9;

    int idx0 = (reward[row0] != 0) ? 1 : 0;
    int idx1 = (row0 + 1 < nrows) ? ((reward[row0 + 1] != 0) ? 1 : 0) : 0;
    int idx2 = (row0 + 2 < nrows) ? ((reward[row0 + 2] != 0) ? 1 : 0) : 0;

    float a0 = W[2 * idx0], b0 = W[2 * idx0 + 1];
    float a1 = W[2 * idx1], b1 = W[2 * idx1 + 1];
    float a2 = W[2 * idx2], b2 = W[2 * idx2 + 1];

    // Offsets k*256, k=0..5: k=0,1 -> row0 ; k=2,3 -> row1 ; k=4,5 -> row2.
    int i0 = blk + tid;            // row0 first half
    int i1 = i0 + 256;             // row0 second half
    int i2 = i0 + 512;             // row1 first half
    int i3 = i0 + 768;             // row1 second half
    int i4 = i0 + 1024;            // row2 first half
    int i5 = i0 + 1280;            // row2 second half

    bool q01 = (i1 < n4);          // row0 fully in range iff i1 < n4
    bool q23 = (i3 < n4);
    bool q45 = (i5 < n4);

    float4 x0, x1, x2, x3, x4, x5, y0, y1, y2, y3, y4, y5;
    if (q01) { x0 = X[i0]; x1 = X[i1]; y0 = Y[i0]; y1 = Y[i1]; }
    if (q23) { x2 = X[i2]; x3 = X[i3]; y2 = Y[i2]; y3 = Y[i3]; }
    if (q45) { x4 = X[i4]; x5 = X[i5]; y4 = Y[i4]; y5 = Y[i5]; }

    float4 o;
    if (q01) {
        o.x = fmaf(x0.x, a0, y0.x * b0); o.y = fmaf(x0.y, a0, y0.y * b0);
        o.z = fmaf(x0.z, a0, y0.z * b0); o.w = fmaf(x0.w, a0, y0.w * b0);
        out[i0] = o;
        o.x = fmaf(x1.x, a0, y1.x * b0); o.y = fmaf(x1.y, a0, y1.y * b0);
        o.z = fmaf(x1.z, a0, y1.z * b0); o.w = fmaf(x1.w, a0, y1.w * b0);
        out[i1] = o;
    }
    if (q23) {
        o.x = fmaf(x2.x, a1, y2.x * b1); o.y = fmaf(x2.y, a1, y2.y * b1);
        o.z = fmaf(x2.z, a1, y2.z * b1); o.w = fmaf(x2.w, a1, y2.w * b1);
        out[i2] = o;
        o.x = fmaf(x3.x, a1, y3.x * b1); o.y = fmaf(x3.y, a1, y3.y * b1);
        o.z = fmaf(x3.z, a1, y3.z * b1); o.w = fmaf(x3.w, a1, y3.w * b1);
        out[i3] = o;
    }
    if (q45) {
        o.x = fmaf(x4.x, a2, y4.x * b2); o.y = fmaf(x4.y, a2, y4.y * b2);
        o.z = fmaf(x4.z, a2, y4.z * b2); o.w = fmaf(x4.w, a2, y4.w * b2);
        out[i4] = o;
        o.x = fmaf(x5.x, a2, y5.x * b2); o.y = fmaf(x5.y, a2, y5.y * b2);
        o.z = fmaf(x5.z, a2, y5.z * b2); o.w = fmaf(x5.w, a2, y5.w * b2);
        out[i5] = o;
    }
}

extern "C" void kernel_launch(void* const* d_in, const int* in_sizes, int n_in,
                              void* d_out, int out_size)
{
    const float4* X      = (const float4*)d_in[0];
    const float4* Y      = (const float4*)d_in[1];
    const int*    reward = (const int*)d_in[2];
    const float*  W      = (const float*)d_in[3];
    float4*       out    = (float4*)d_out;

    int n  = out_size;              // 4*4096*2048 = 33554432 fp32
    int n4 = n / 4;                 // 8388608 float4
    int blocks = (n4 + 1535) / 1536; // 5462 blocks (3 rows each, last partial)

    blend_kernel_m6b<<<blocks, 256>>>(X, Y, reward, W, out, n4);
}